// round 8
// baseline (speedup 1.0000x reference)
#include <cuda_runtime.h>
#include <cuda_fp16.h>
#include <stdint.h>

// Problem shape: 100000 users + 50000 items, D=64, E=2M.
#define MAXN 150016
#define MAXE 2000000
#define D 64
#define ROW_U2 16              // 64 halfs = 16 uint2 per row
#define SCAN_T 1024
#define MAX_BLOCKS 256
#define NLAYERS 4

// -------- static device scratch --------
__device__ int    g_deg[MAXN];
__device__ float  g_dis[MAXN];
__device__ float  g_inv[MAXN];          // sqrt(deg), 0 if deg==0
__device__ int    g_off[MAXN + 1];
__device__ int    g_cur[MAXN];
__device__ int    g_csr[MAXE];
__device__ int    g_bsum[MAX_BLOCKS];
__device__ int    g_flag[MAX_BLOCKS];
// t_0..t_4 message buffers, fp16: t_k = dis * e_k
__device__ __half g_t[(size_t)(NLAYERS + 1) * MAXN * D];

// -------- kernels --------

// 4 edges per thread via int4.
__global__ void count_deg_kernel(const int* __restrict__ dst, int E, int N) {
    if (threadIdx.x == 0 && blockIdx.x < MAX_BLOCKS) g_flag[blockIdx.x] = 0;
    int q = blockIdx.x * blockDim.x + threadIdx.x;   // quad index
    int base = q << 2;
    if (base + 3 < E) {
        int4 d4 = *(const int4*)&dst[base];
        if ((unsigned)d4.x < (unsigned)N) atomicAdd(&g_deg[d4.x], 1);
        if ((unsigned)d4.y < (unsigned)N) atomicAdd(&g_deg[d4.y], 1);
        if ((unsigned)d4.z < (unsigned)N) atomicAdd(&g_deg[d4.z], 1);
        if ((unsigned)d4.w < (unsigned)N) atomicAdd(&g_deg[d4.w], 1);
    } else {
        for (int e = base; e < E; e++) {
            int d = dst[e];
            if ((unsigned)d < (unsigned)N) atomicAdd(&g_deg[d], 1);
        }
    }
}

// Single-pass scan (decoupled lookback) + finalize + t0 init.
__global__ void __launch_bounds__(SCAN_T)
scan_fused_kernel(const float* __restrict__ emb_users,
                  const float* __restrict__ emb_items,
                  int nu_elems, int N) {
    __shared__ int wsum[32];
    __shared__ int block_prefix_s;
    int t = threadIdx.x;
    int b = blockIdx.x;
    int i = b * SCAN_T + t;
    int v = (i < N) ? g_deg[i] : 0;

    int x = v;
    #pragma unroll
    for (int off = 1; off < 32; off <<= 1) {
        int y = __shfl_up_sync(0xffffffff, x, off);
        if ((t & 31) >= off) x += y;
    }
    if ((t & 31) == 31) wsum[t >> 5] = x;
    __syncthreads();

    if (t < 32) {
        int w = wsum[t];
        #pragma unroll
        for (int off = 1; off < 32; off <<= 1) {
            int y = __shfl_up_sync(0xffffffff, w, off);
            if (t >= off) w += y;
        }
        wsum[t] = w;
    }
    __syncthreads();

    int base = (t >= 32) ? wsum[(t >> 5) - 1] : 0;
    int incl_local = base + x;
    int block_total = wsum[31];

    if (t == 0) {
        g_bsum[b] = block_total;
        __threadfence();
        atomicExch(&g_flag[b], 1);
    }
    if (t < 32) {
        int acc = 0;
        for (int pb = t; pb < b; pb += 32) {
            while (atomicAdd(&g_flag[pb], 0) == 0) { }
            acc += atomicAdd(&g_bsum[pb], 0);
        }
        #pragma unroll
        for (int off = 16; off > 0; off >>= 1)
            acc += __shfl_down_sync(0xffffffff, acc, off);
        if (t == 0) block_prefix_s = acc;
    }
    __syncthreads();
    int bp = block_prefix_s;

    if (i < N) {
        int incl = bp + incl_local;
        g_off[i + 1] = incl;
        g_cur[i]     = incl - v;
        float fd = (float)v;
        g_dis[i] = (v > 0) ? rsqrtf(fd) : 0.0f;
        g_inv[i] = (v > 0) ? sqrtf(fd) : 0.0f;
        if (i == 0) g_off[0] = 0;
    }
    __syncthreads();

    int chunk_nodes = min(SCAN_T, N - b * SCAN_T);
    if (chunk_nodes <= 0) return;
    int elems = chunk_nodes * D;
    size_t ebase = (size_t)b * SCAN_T * D;
    for (int k = t; k < elems; k += SCAN_T) {
        size_t idx = ebase + k;
        float v0 = (idx < (size_t)nu_elems) ? emb_users[idx]
                                            : emb_items[idx - nu_elems];
        g_t[idx] = __float2half(g_dis[idx >> 6] * v0);
    }
}

// 4 edges per thread via int4.
__global__ void scatter_kernel(const int* __restrict__ src,
                               const int* __restrict__ dst, int E, int N) {
    int q = blockIdx.x * blockDim.x + threadIdx.x;
    int base = q << 2;
    if (base + 3 < E) {
        int4 s4 = *(const int4*)&src[base];
        int4 d4 = *(const int4*)&dst[base];
        #define SC1(ss, dd) \
            if ((unsigned)(dd) < (unsigned)N && (unsigned)(ss) < (unsigned)N) { \
                int pos = atomicAdd(&g_cur[dd], 1); \
                if ((unsigned)pos < (unsigned)MAXE) g_csr[pos] = (ss); }
        SC1(s4.x, d4.x) SC1(s4.y, d4.y) SC1(s4.z, d4.z) SC1(s4.w, d4.w)
        #undef SC1
    } else {
        for (int e = base; e < E; e++) {
            int d = dst[e];
            int s = src[e];
            if ((unsigned)d < (unsigned)N && (unsigned)s < (unsigned)N) {
                int pos = atomicAdd(&g_cur[d], 1);
                if ((unsigned)pos < (unsigned)MAXE) g_csr[pos] = s;
            }
        }
    }
}

// One layer: reads t_{k-1}, writes t_k. Two nodes per warp (16 lanes each),
// each lane gathers 8B. Main loop: 8 edges in flight (two int4 index loads).
__global__ void __launch_bounds__(256)
layer_kernel(int N, int kin) {
    int gtid = blockIdx.x * blockDim.x + threadIdx.x;
    int w    = gtid >> 5;
    int lane = gtid & 31;
    int node = (w << 1) | (lane >> 4);
    int sub  = lane & 15;
    if (node >= N) return;

    const uint2* __restrict__ tin  =
        (const uint2*)(g_t + (size_t)kin * MAXN * D);
    uint2* __restrict__ tout =
        (uint2*)(g_t + (size_t)(kin + 1) * MAXN * D);

    int s = g_off[node];
    int e = g_off[node + 1];

    float ax = 0.f, ay = 0.f, az = 0.f, aw = 0.f;
    int p = s;

    // head: align p to 4 (fp32 accumulate)
    for (; p < e && (p & 3); p++) {
        int u0 = g_csr[p];
        uint2 r0 = __ldg(&tin[(size_t)u0 * ROW_U2 + sub]);
        float2 a0 = __half22float2(*(__half2*)&r0.x);
        float2 b0 = __half22float2(*(__half2*)&r0.y);
        ax += a0.x; ay += a0.y; az += b0.x; aw += b0.y;
    }

    // main: 8 edges per iteration, 8 gathers in flight
    for (; p + 7 < e; p += 8) {
        int4 u = *(const int4*)&g_csr[p];
        int4 v = *(const int4*)&g_csr[p + 4];
        uint2 r0 = __ldg(&tin[(size_t)u.x * ROW_U2 + sub]);
        uint2 r1 = __ldg(&tin[(size_t)u.y * ROW_U2 + sub]);
        uint2 r2 = __ldg(&tin[(size_t)u.z * ROW_U2 + sub]);
        uint2 r3 = __ldg(&tin[(size_t)u.w * ROW_U2 + sub]);
        uint2 r4 = __ldg(&tin[(size_t)v.x * ROW_U2 + sub]);
        uint2 r5 = __ldg(&tin[(size_t)v.y * ROW_U2 + sub]);
        uint2 r6 = __ldg(&tin[(size_t)v.z * ROW_U2 + sub]);
        uint2 r7 = __ldg(&tin[(size_t)v.w * ROW_U2 + sub]);
        // fp16 pairwise tree over 8 values
        __half2 lo01 = __hadd2(*(__half2*)&r0.x, *(__half2*)&r1.x);
        __half2 lo23 = __hadd2(*(__half2*)&r2.x, *(__half2*)&r3.x);
        __half2 lo45 = __hadd2(*(__half2*)&r4.x, *(__half2*)&r5.x);
        __half2 lo67 = __hadd2(*(__half2*)&r6.x, *(__half2*)&r7.x);
        __half2 hi01 = __hadd2(*(__half2*)&r0.y, *(__half2*)&r1.y);
        __half2 hi23 = __hadd2(*(__half2*)&r2.y, *(__half2*)&r3.y);
        __half2 hi45 = __hadd2(*(__half2*)&r4.y, *(__half2*)&r5.y);
        __half2 hi67 = __hadd2(*(__half2*)&r6.y, *(__half2*)&r7.y);
        __half2 lo_a = __hadd2(lo01, lo23);
        __half2 lo_b = __hadd2(lo45, lo67);
        __half2 hi_a = __hadd2(hi01, hi23);
        __half2 hi_b = __hadd2(hi45, hi67);
        __half2 lo = __hadd2(lo_a, lo_b);
        __half2 hi = __hadd2(hi_a, hi_b);
        float2 fl = __half22float2(lo);
        float2 fh = __half22float2(hi);
        ax += fl.x; ay += fl.y; az += fh.x; aw += fh.y;
    }

    // 4-edge group
    if (p + 3 < e) {
        int4 u = *(const int4*)&g_csr[p];
        uint2 r0 = __ldg(&tin[(size_t)u.x * ROW_U2 + sub]);
        uint2 r1 = __ldg(&tin[(size_t)u.y * ROW_U2 + sub]);
        uint2 r2 = __ldg(&tin[(size_t)u.z * ROW_U2 + sub]);
        uint2 r3 = __ldg(&tin[(size_t)u.w * ROW_U2 + sub]);
        __half2 lo01 = __hadd2(*(__half2*)&r0.x, *(__half2*)&r1.x);
        __half2 lo23 = __hadd2(*(__half2*)&r2.x, *(__half2*)&r3.x);
        __half2 hi01 = __hadd2(*(__half2*)&r0.y, *(__half2*)&r1.y);
        __half2 hi23 = __hadd2(*(__half2*)&r2.y, *(__half2*)&r3.y);
        float2 fl = __half22float2(__hadd2(lo01, lo23));
        float2 fh = __half22float2(__hadd2(hi01, hi23));
        ax += fl.x; ay += fl.y; az += fh.x; aw += fh.y;
        p += 4;
    }

    // tail
    for (; p < e; p++) {
        int u0 = g_csr[p];
        uint2 r0 = __ldg(&tin[(size_t)u0 * ROW_U2 + sub]);
        float2 a0 = __half22float2(*(__half2*)&r0.x);
        float2 b0 = __half22float2(*(__half2*)&r0.y);
        ax += a0.x; ay += a0.y; az += b0.x; aw += b0.y;
    }

    float dv = g_dis[node];
    float d2 = dv * dv;          // t_next = dis^2 * sum
    uint2 o;
    __half2 lo = __floats2half2_rn(d2 * ax, d2 * ay);
    __half2 hi = __floats2half2_rn(d2 * az, d2 * aw);
    o.x = *(uint32_t*)&lo;
    o.y = *(uint32_t*)&hi;
    tout[(size_t)node * ROW_U2 + sub] = o;
}

// out = (emb0 + sqrt(deg) * (t1+t2+t3+t4)) / 25.
__global__ void final_kernel(const float* __restrict__ emb_users,
                             const float* __restrict__ emb_items,
                             float* __restrict__ out,
                             int nu_pairs, int total_pairs) {
    int idx = blockIdx.x * blockDim.x + threadIdx.x;
    if (idx >= total_pairs) return;
    int node = idx >> 5;

    const __half2* t1 = (const __half2*)(g_t + (size_t)1 * MAXN * D);
    const __half2* t2 = (const __half2*)(g_t + (size_t)2 * MAXN * D);
    const __half2* t3 = (const __half2*)(g_t + (size_t)3 * MAXN * D);
    const __half2* t4 = (const __half2*)(g_t + (size_t)4 * MAXN * D);

    float2 s1 = __half22float2(t1[idx]);
    float2 s2 = __half22float2(t2[idx]);
    float2 s3 = __half22float2(t3[idx]);
    float2 s4 = __half22float2(t4[idx]);

    const float2* embu = (const float2*)emb_users;
    const float2* embi = (const float2*)emb_items;
    float2 e0 = (idx < nu_pairs) ? embu[idx] : embi[idx - nu_pairs];

    float inv = g_inv[node];
    const float sc = 1.0f / 25.0f;
    float2 r;
    r.x = (e0.x + inv * (s1.x + s2.x + s3.x + s4.x)) * sc;
    r.y = (e0.y + inv * (s1.y + s2.y + s3.y + s4.y)) * sc;
    ((float2*)out)[idx] = r;
}

// -------- launch --------
extern "C" void kernel_launch(void* const* d_in, const int* in_sizes, int n_in,
                              void* d_out, int out_size) {
    const float* emb_users = (const float*)d_in[0];
    const float* emb_items = (const float*)d_in[1];
    const int*   edge      = (const int*)d_in[2];   // int32

    int nu_elems = in_sizes[0];
    int ni_elems = in_sizes[1];
    int E        = in_sizes[2] / 2;
    int NU = nu_elems / D;
    int NI = ni_elems / D;
    int N  = NU + NI;

    const int* src = edge;
    const int* dst = edge + E;
    float* out = (float*)d_out;

    const int T = 256;
    int nScanBlocks = (N + SCAN_T - 1) / SCAN_T;   // 147 <= 148 SMs

    void* deg_ptr = nullptr;
    cudaGetSymbolAddress(&deg_ptr, g_deg);
    cudaMemsetAsync(deg_ptr, 0, (size_t)N * sizeof(int));

    int quads = (E + 3) / 4;
    count_deg_kernel<<<(quads + T - 1) / T, T>>>(dst, E, N);
    scan_fused_kernel<<<nScanBlocks, SCAN_T>>>(emb_users, emb_items, nu_elems, N);
    scatter_kernel<<<(quads + T - 1) / T, T>>>(src, dst, E, N);

    int layer_blocks = (N * 16 + T - 1) / T;   // 2 nodes per warp
    layer_kernel<<<layer_blocks, T>>>(N, 0);
    layer_kernel<<<layer_blocks, T>>>(N, 1);
    layer_kernel<<<layer_blocks, T>>>(N, 2);
    layer_kernel<<<layer_blocks, T>>>(N, 3);

    int total_pairs = N * (D / 2);
    final_kernel<<<(total_pairs + T - 1) / T, T>>>(emb_users, emb_items, out,
                                                   nu_elems / 2, total_pairs);
}

// round 9
// speedup vs baseline: 1.0464x; 1.0464x over previous
#include <cuda_runtime.h>
#include <cuda_fp16.h>
#include <stdint.h>

// Problem shape: 100000 users + 50000 items, D=64, E=2M.
#define MAXN 150016
#define MAXE 2000000
#define D 64
#define ROW_U2 16              // 64 halfs = 16 uint2 per row
#define SCAN_T 1024
#define MAX_BLOCKS 256
#define NLAYERS 4

// -------- static device scratch --------
__device__ int    g_deg[MAXN];
__device__ float  g_dis[MAXN];
__device__ float  g_inv[MAXN];          // sqrt(deg), 0 if deg==0
__device__ int    g_off[MAXN + 1];
__device__ int    g_cur[MAXN];
__device__ int    g_csr[MAXE];
__device__ int    g_bsum[MAX_BLOCKS];
__device__ int    g_flag[MAX_BLOCKS];
// t_0..t_3 message buffers, fp16: t_k = dis * e_k (t4 never materialized)
__device__ __half g_t[(size_t)NLAYERS * MAXN * D];

// L2-only gather (bypass L1: random access, no reuse at L1 level)
__device__ __forceinline__ uint2 ldcg_u2(const uint2* p) {
    uint2 r;
    asm("ld.global.cg.v2.u32 {%0,%1}, [%2];" : "=r"(r.x), "=r"(r.y) : "l"(p));
    return r;
}

// -------- kernels --------

// 4 edges per thread via int4.
__global__ void count_deg_kernel(const int* __restrict__ dst, int E, int N) {
    if (threadIdx.x == 0 && blockIdx.x < MAX_BLOCKS) g_flag[blockIdx.x] = 0;
    int q = blockIdx.x * blockDim.x + threadIdx.x;
    int base = q << 2;
    if (base + 3 < E) {
        int4 d4 = *(const int4*)&dst[base];
        if ((unsigned)d4.x < (unsigned)N) atomicAdd(&g_deg[d4.x], 1);
        if ((unsigned)d4.y < (unsigned)N) atomicAdd(&g_deg[d4.y], 1);
        if ((unsigned)d4.z < (unsigned)N) atomicAdd(&g_deg[d4.z], 1);
        if ((unsigned)d4.w < (unsigned)N) atomicAdd(&g_deg[d4.w], 1);
    } else {
        for (int e = base; e < E; e++) {
            int d = dst[e];
            if ((unsigned)d < (unsigned)N) atomicAdd(&g_deg[d], 1);
        }
    }
}

// Single-pass scan (decoupled lookback) + finalize + t0 init.
__global__ void __launch_bounds__(SCAN_T)
scan_fused_kernel(const float* __restrict__ emb_users,
                  const float* __restrict__ emb_items,
                  int nu_elems, int N) {
    __shared__ int wsum[32];
    __shared__ int block_prefix_s;
    int t = threadIdx.x;
    int b = blockIdx.x;
    int i = b * SCAN_T + t;
    int v = (i < N) ? g_deg[i] : 0;

    int x = v;
    #pragma unroll
    for (int off = 1; off < 32; off <<= 1) {
        int y = __shfl_up_sync(0xffffffff, x, off);
        if ((t & 31) >= off) x += y;
    }
    if ((t & 31) == 31) wsum[t >> 5] = x;
    __syncthreads();

    if (t < 32) {
        int w = wsum[t];
        #pragma unroll
        for (int off = 1; off < 32; off <<= 1) {
            int y = __shfl_up_sync(0xffffffff, w, off);
            if (t >= off) w += y;
        }
        wsum[t] = w;
    }
    __syncthreads();

    int base = (t >= 32) ? wsum[(t >> 5) - 1] : 0;
    int incl_local = base + x;
    int block_total = wsum[31];

    if (t == 0) {
        g_bsum[b] = block_total;
        __threadfence();
        atomicExch(&g_flag[b], 1);
    }
    if (t < 32) {
        int acc = 0;
        for (int pb = t; pb < b; pb += 32) {
            while (atomicAdd(&g_flag[pb], 0) == 0) { }
            acc += atomicAdd(&g_bsum[pb], 0);
        }
        #pragma unroll
        for (int off = 16; off > 0; off >>= 1)
            acc += __shfl_down_sync(0xffffffff, acc, off);
        if (t == 0) block_prefix_s = acc;
    }
    __syncthreads();
    int bp = block_prefix_s;

    if (i < N) {
        int incl = bp + incl_local;
        g_off[i + 1] = incl;
        g_cur[i]     = incl - v;
        float fd = (float)v;
        g_dis[i] = (v > 0) ? rsqrtf(fd) : 0.0f;
        g_inv[i] = (v > 0) ? sqrtf(fd) : 0.0f;
        if (i == 0) g_off[0] = 0;
    }
    __syncthreads();

    int chunk_nodes = min(SCAN_T, N - b * SCAN_T);
    if (chunk_nodes <= 0) return;
    int elems = chunk_nodes * D;
    size_t ebase = (size_t)b * SCAN_T * D;
    for (int k = t; k < elems; k += SCAN_T) {
        size_t idx = ebase + k;
        float v0 = (idx < (size_t)nu_elems) ? emb_users[idx]
                                            : emb_items[idx - nu_elems];
        g_t[idx] = __float2half(g_dis[idx >> 6] * v0);
    }
}

// 4 edges per thread via int4.
__global__ void scatter_kernel(const int* __restrict__ src,
                               const int* __restrict__ dst, int E, int N) {
    int q = blockIdx.x * blockDim.x + threadIdx.x;
    int base = q << 2;
    if (base + 3 < E) {
        int4 s4 = *(const int4*)&src[base];
        int4 d4 = *(const int4*)&dst[base];
        #define SC1(ss, dd) \
            if ((unsigned)(dd) < (unsigned)N && (unsigned)(ss) < (unsigned)N) { \
                int pos = atomicAdd(&g_cur[dd], 1); \
                if ((unsigned)pos < (unsigned)MAXE) g_csr[pos] = (ss); }
        SC1(s4.x, d4.x) SC1(s4.y, d4.y) SC1(s4.z, d4.z) SC1(s4.w, d4.w)
        #undef SC1
    } else {
        for (int e = base; e < E; e++) {
            int d = dst[e];
            int s = src[e];
            if ((unsigned)d < (unsigned)N && (unsigned)s < (unsigned)N) {
                int pos = atomicAdd(&g_cur[d], 1);
                if ((unsigned)pos < (unsigned)MAXE) g_csr[pos] = s;
            }
        }
    }
}

// Shared gather body (R7 shape): returns fp32 4-vector sum over neighbor list.
__device__ __forceinline__ void gather_sum(const uint2* __restrict__ tin,
                                           int s, int e, int sub,
                                           float& ax, float& ay,
                                           float& az, float& aw) {
    ax = ay = az = aw = 0.f;
    int p = s;
    // head: align to 4
    for (; p < e && (p & 3); p++) {
        int u0 = g_csr[p];
        uint2 r0 = ldcg_u2(&tin[(size_t)u0 * ROW_U2 + sub]);
        float2 a0 = __half22float2(*(__half2*)&r0.x);
        float2 b0 = __half22float2(*(__half2*)&r0.y);
        ax += a0.x; ay += a0.y; az += b0.x; aw += b0.y;
    }
    // main: 4 edges per iteration
    for (; p + 3 < e; p += 4) {
        int4 u = *(const int4*)&g_csr[p];
        uint2 r0 = ldcg_u2(&tin[(size_t)u.x * ROW_U2 + sub]);
        uint2 r1 = ldcg_u2(&tin[(size_t)u.y * ROW_U2 + sub]);
        uint2 r2 = ldcg_u2(&tin[(size_t)u.z * ROW_U2 + sub]);
        uint2 r3 = ldcg_u2(&tin[(size_t)u.w * ROW_U2 + sub]);
        __half2 lo01 = __hadd2(*(__half2*)&r0.x, *(__half2*)&r1.x);
        __half2 lo23 = __hadd2(*(__half2*)&r2.x, *(__half2*)&r3.x);
        __half2 hi01 = __hadd2(*(__half2*)&r0.y, *(__half2*)&r1.y);
        __half2 hi23 = __hadd2(*(__half2*)&r2.y, *(__half2*)&r3.y);
        float2 fl = __half22float2(__hadd2(lo01, lo23));
        float2 fh = __half22float2(__hadd2(hi01, hi23));
        ax += fl.x; ay += fl.y; az += fh.x; aw += fh.y;
    }
    // tail
    for (; p < e; p++) {
        int u0 = g_csr[p];
        uint2 r0 = ldcg_u2(&tin[(size_t)u0 * ROW_U2 + sub]);
        float2 a0 = __half22float2(*(__half2*)&r0.x);
        float2 b0 = __half22float2(*(__half2*)&r0.y);
        ax += a0.x; ay += a0.y; az += b0.x; aw += b0.y;
    }
}

// Layers 1..3: read t_{k-1}, write t_k. Two nodes per warp, 8B per lane.
__global__ void __launch_bounds__(256)
layer_kernel(int N, int kin) {
    int gtid = blockIdx.x * blockDim.x + threadIdx.x;
    int w    = gtid >> 5;
    int lane = gtid & 31;
    int node = (w << 1) | (lane >> 4);
    int sub  = lane & 15;
    if (node >= N) return;

    const uint2* __restrict__ tin =
        (const uint2*)(g_t + (size_t)kin * MAXN * D);
    uint2* __restrict__ tout =
        (uint2*)(g_t + (size_t)(kin + 1) * MAXN * D);

    float ax, ay, az, aw;
    gather_sum(tin, g_off[node], g_off[node + 1], sub, ax, ay, az, aw);

    float dv = g_dis[node];
    float d2 = dv * dv;          // t_next = dis^2 * sum
    uint2 o;
    __half2 lo = __floats2half2_rn(d2 * ax, d2 * ay);
    __half2 hi = __floats2half2_rn(d2 * az, d2 * aw);
    o.x = *(uint32_t*)&lo;
    o.y = *(uint32_t*)&hi;
    tout[(size_t)node * ROW_U2 + sub] = o;
}

// Layer 4 fused with the final combine:
// out = (e0 + inv*(t1+t2+t3) + dis*sum) / 25   (inv*t4 = inv*dis^2*sum = dis*sum)
__global__ void __launch_bounds__(256)
layer_final_kernel(const float* __restrict__ emb_users,
                   const float* __restrict__ emb_items,
                   float* __restrict__ out, int N, int NU) {
    int gtid = blockIdx.x * blockDim.x + threadIdx.x;
    int w    = gtid >> 5;
    int lane = gtid & 31;
    int node = (w << 1) | (lane >> 4);
    int sub  = lane & 15;
    if (node >= N) return;

    const uint2* __restrict__ t1 = (const uint2*)(g_t + (size_t)1 * MAXN * D);
    const uint2* __restrict__ t2 = (const uint2*)(g_t + (size_t)2 * MAXN * D);
    const uint2* __restrict__ t3 = (const uint2*)(g_t + (size_t)3 * MAXN * D);

    float ax, ay, az, aw;
    gather_sum(t3, g_off[node], g_off[node + 1], sub, ax, ay, az, aw);

    size_t oidx = (size_t)node * ROW_U2 + sub;
    uint2 w1 = t1[oidx];
    uint2 w2 = t2[oidx];
    uint2 w3 = ((const uint2*)(g_t + (size_t)2 * MAXN * D))[oidx]; // placeholder (see below)
    // NOTE: t3 partial sum must come from buffer index 3? t buffers: t0..t3.
    // gather input for layer4 is t3; the historical sums needed are t1,t2,t3.
    w3 = t3[oidx];

    float2 f1a = __half22float2(*(__half2*)&w1.x);
    float2 f1b = __half22float2(*(__half2*)&w1.y);
    float2 f2a = __half22float2(*(__half2*)&w2.x);
    float2 f2b = __half22float2(*(__half2*)&w2.y);
    float2 f3a = __half22float2(*(__half2*)&w3.x);
    float2 f3b = __half22float2(*(__half2*)&w3.y);

    float sx = f1a.x + f2a.x + f3a.x;
    float sy = f1a.y + f2a.y + f3a.y;
    float sz = f1b.x + f2b.x + f3b.x;
    float sw = f1b.y + f2b.y + f3b.y;

    // e0: 4 contiguous fp32 at element offset node*64 + sub*4
    size_t ebase = (size_t)node * D + sub * 4;
    float4 e0;
    if (node < NU) {
        e0 = *(const float4*)&emb_users[ebase];
    } else {
        e0 = *(const float4*)&emb_items[ebase - (size_t)NU * D];
    }

    float dv  = g_dis[node];
    float inv = g_inv[node];
    const float sc = 1.0f / 25.0f;
    float4 r;
    r.x = (e0.x + inv * sx + dv * ax) * sc;
    r.y = (e0.y + inv * sy + dv * ay) * sc;
    r.z = (e0.z + inv * sz + dv * az) * sc;
    r.w = (e0.w + inv * sw + dv * aw) * sc;
    *(float4*)&out[ebase] = r;
}

// -------- launch --------
extern "C" void kernel_launch(void* const* d_in, const int* in_sizes, int n_in,
                              void* d_out, int out_size) {
    const float* emb_users = (const float*)d_in[0];
    const float* emb_items = (const float*)d_in[1];
    const int*   edge      = (const int*)d_in[2];   // int32

    int nu_elems = in_sizes[0];
    int ni_elems = in_sizes[1];
    int E        = in_sizes[2] / 2;
    int NU = nu_elems / D;
    int NI = ni_elems / D;
    int N  = NU + NI;

    const int* src = edge;
    const int* dst = edge + E;
    float* out = (float*)d_out;

    const int T = 256;
    int nScanBlocks = (N + SCAN_T - 1) / SCAN_T;   // 147 <= 148 SMs

    void* deg_ptr = nullptr;
    cudaGetSymbolAddress(&deg_ptr, g_deg);
    cudaMemsetAsync(deg_ptr, 0, (size_t)N * sizeof(int));

    int quads = (E + 3) / 4;
    count_deg_kernel<<<(quads + T - 1) / T, T>>>(dst, E, N);
    scan_fused_kernel<<<nScanBlocks, SCAN_T>>>(emb_users, emb_items, nu_elems, N);
    scatter_kernel<<<(quads + T - 1) / T, T>>>(src, dst, E, N);

    int layer_blocks = (N * 16 + T - 1) / T;   // 2 nodes per warp
    layer_kernel<<<layer_blocks, T>>>(N, 0);   // t0 -> t1
    layer_kernel<<<layer_blocks, T>>>(N, 1);   // t1 -> t2
    layer_kernel<<<layer_blocks, T>>>(N, 2);   // t2 -> t3
    layer_final_kernel<<<layer_blocks, T>>>(emb_users, emb_items, out, N, NU);
}

// round 10
// speedup vs baseline: 1.2099x; 1.1562x over previous
#include <cuda_runtime.h>
#include <cuda_fp16.h>
#include <stdint.h>

// Problem shape: 100000 users + 50000 items, D=64, E=2M.
#define MAXN 150016
#define MAXE 2000000
#define D 64
#define ROW_U2 16              // 64 halfs = 16 uint2 per row
#define SCAN_T 1024
#define MAX_BLOCKS 256
#define NLAYERS 4

// -------- static device scratch --------
__device__ int    g_deg[MAXN];
__device__ float  g_dis[MAXN];
__device__ float  g_inv[MAXN];          // sqrt(deg), 0 if deg==0
__device__ int    g_off[MAXN + 1];
__device__ int    g_cur[MAXN];
__device__ int    g_csr[MAXE];
__device__ int    g_bsum[MAX_BLOCKS];
__device__ int    g_flag[MAX_BLOCKS];
// t_0..t_3 message buffers, fp16: t_k = dis * e_k (t4 never materialized)
__device__ __half g_t[(size_t)NLAYERS * MAXN * D];

// -------- kernels --------

// 4 edges per thread via int4.
__global__ void count_deg_kernel(const int* __restrict__ dst, int E, int N) {
    if (threadIdx.x == 0 && blockIdx.x < MAX_BLOCKS) g_flag[blockIdx.x] = 0;
    int q = blockIdx.x * blockDim.x + threadIdx.x;
    int base = q << 2;
    if (base + 3 < E) {
        int4 d4 = *(const int4*)&dst[base];
        if ((unsigned)d4.x < (unsigned)N) atomicAdd(&g_deg[d4.x], 1);
        if ((unsigned)d4.y < (unsigned)N) atomicAdd(&g_deg[d4.y], 1);
        if ((unsigned)d4.z < (unsigned)N) atomicAdd(&g_deg[d4.z], 1);
        if ((unsigned)d4.w < (unsigned)N) atomicAdd(&g_deg[d4.w], 1);
    } else {
        for (int e = base; e < E; e++) {
            int d = dst[e];
            if ((unsigned)d < (unsigned)N) atomicAdd(&g_deg[d], 1);
        }
    }
}

// Single-pass scan (decoupled lookback) + finalize + t0 init.
__global__ void __launch_bounds__(SCAN_T)
scan_fused_kernel(const float* __restrict__ emb_users,
                  const float* __restrict__ emb_items,
                  int nu_elems, int N) {
    __shared__ int wsum[32];
    __shared__ int block_prefix_s;
    int t = threadIdx.x;
    int b = blockIdx.x;
    int i = b * SCAN_T + t;
    int v = (i < N) ? g_deg[i] : 0;

    int x = v;
    #pragma unroll
    for (int off = 1; off < 32; off <<= 1) {
        int y = __shfl_up_sync(0xffffffff, x, off);
        if ((t & 31) >= off) x += y;
    }
    if ((t & 31) == 31) wsum[t >> 5] = x;
    __syncthreads();

    if (t < 32) {
        int w = wsum[t];
        #pragma unroll
        for (int off = 1; off < 32; off <<= 1) {
            int y = __shfl_up_sync(0xffffffff, w, off);
            if (t >= off) w += y;
        }
        wsum[t] = w;
    }
    __syncthreads();

    int base = (t >= 32) ? wsum[(t >> 5) - 1] : 0;
    int incl_local = base + x;
    int block_total = wsum[31];

    if (t == 0) {
        g_bsum[b] = block_total;
        __threadfence();
        atomicExch(&g_flag[b], 1);
    }
    if (t < 32) {
        int acc = 0;
        for (int pb = t; pb < b; pb += 32) {
            while (atomicAdd(&g_flag[pb], 0) == 0) { }
            acc += atomicAdd(&g_bsum[pb], 0);
        }
        #pragma unroll
        for (int off = 16; off > 0; off >>= 1)
            acc += __shfl_down_sync(0xffffffff, acc, off);
        if (t == 0) block_prefix_s = acc;
    }
    __syncthreads();
    int bp = block_prefix_s;

    if (i < N) {
        int incl = bp + incl_local;
        g_off[i + 1] = incl;
        g_cur[i]     = incl - v;
        float fd = (float)v;
        g_dis[i] = (v > 0) ? rsqrtf(fd) : 0.0f;
        g_inv[i] = (v > 0) ? sqrtf(fd) : 0.0f;
        if (i == 0) g_off[0] = 0;
    }
    __syncthreads();

    int chunk_nodes = min(SCAN_T, N - b * SCAN_T);
    if (chunk_nodes <= 0) return;
    int elems = chunk_nodes * D;
    size_t ebase = (size_t)b * SCAN_T * D;
    for (int k = t; k < elems; k += SCAN_T) {
        size_t idx = ebase + k;
        float v0 = (idx < (size_t)nu_elems) ? emb_users[idx]
                                            : emb_items[idx - nu_elems];
        g_t[idx] = __float2half(g_dis[idx >> 6] * v0);
    }
}

// 4 edges per thread via int4.
__global__ void scatter_kernel(const int* __restrict__ src,
                               const int* __restrict__ dst, int E, int N) {
    int q = blockIdx.x * blockDim.x + threadIdx.x;
    int base = q << 2;
    if (base + 3 < E) {
        int4 s4 = *(const int4*)&src[base];
        int4 d4 = *(const int4*)&dst[base];
        #define SC1(ss, dd) \
            if ((unsigned)(dd) < (unsigned)N && (unsigned)(ss) < (unsigned)N) { \
                int pos = atomicAdd(&g_cur[dd], 1); \
                if ((unsigned)pos < (unsigned)MAXE) g_csr[pos] = (ss); }
        SC1(s4.x, d4.x) SC1(s4.y, d4.y) SC1(s4.z, d4.z) SC1(s4.w, d4.w)
        #undef SC1
    } else {
        for (int e = base; e < E; e++) {
            int d = dst[e];
            int s = src[e];
            if ((unsigned)d < (unsigned)N && (unsigned)s < (unsigned)N) {
                int pos = atomicAdd(&g_cur[d], 1);
                if ((unsigned)pos < (unsigned)MAXE) g_csr[pos] = s;
            }
        }
    }
}

// Gather body: __ldg (L1 enabled), 4-deep, software-pipelined index loads.
__device__ __forceinline__ void gather_sum(const uint2* __restrict__ tin,
                                           int s, int e, int sub,
                                           float& ax, float& ay,
                                           float& az, float& aw) {
    ax = ay = az = aw = 0.f;
    int p = s;
    // head: align to 4
    for (; p < e && (p & 3); p++) {
        int u0 = __ldg(&g_csr[p]);
        uint2 r0 = __ldg(&tin[(size_t)u0 * ROW_U2 + sub]);
        float2 a0 = __half22float2(*(__half2*)&r0.x);
        float2 b0 = __half22float2(*(__half2*)&r0.y);
        ax += a0.x; ay += a0.y; az += b0.x; aw += b0.y;
    }
    // main: 4 edges/iter, next index quad prefetched before accumulation
    if (p + 3 < e) {
        int4 u = *(const int4*)&g_csr[p];
        for (;;) {
            int pn = p + 4;
            bool more = (pn + 3 < e);
            int4 un;
            if (more) un = *(const int4*)&g_csr[pn];   // prefetch next quad
            uint2 r0 = __ldg(&tin[(size_t)u.x * ROW_U2 + sub]);
            uint2 r1 = __ldg(&tin[(size_t)u.y * ROW_U2 + sub]);
            uint2 r2 = __ldg(&tin[(size_t)u.z * ROW_U2 + sub]);
            uint2 r3 = __ldg(&tin[(size_t)u.w * ROW_U2 + sub]);
            __half2 lo01 = __hadd2(*(__half2*)&r0.x, *(__half2*)&r1.x);
            __half2 lo23 = __hadd2(*(__half2*)&r2.x, *(__half2*)&r3.x);
            __half2 hi01 = __hadd2(*(__half2*)&r0.y, *(__half2*)&r1.y);
            __half2 hi23 = __hadd2(*(__half2*)&r2.y, *(__half2*)&r3.y);
            float2 fl = __half22float2(__hadd2(lo01, lo23));
            float2 fh = __half22float2(__hadd2(hi01, hi23));
            ax += fl.x; ay += fl.y; az += fh.x; aw += fh.y;
            p = pn;
            if (!more) break;
            u = un;
        }
    }
    // tail
    for (; p < e; p++) {
        int u0 = __ldg(&g_csr[p]);
        uint2 r0 = __ldg(&tin[(size_t)u0 * ROW_U2 + sub]);
        float2 a0 = __half22float2(*(__half2*)&r0.x);
        float2 b0 = __half22float2(*(__half2*)&r0.y);
        ax += a0.x; ay += a0.y; az += b0.x; aw += b0.y;
    }
}

// Layers 1..3: read t_{k-1}, write t_k. Two nodes per warp, 8B per lane.
__global__ void __launch_bounds__(256)
layer_kernel(int N, int kin) {
    int gtid = blockIdx.x * blockDim.x + threadIdx.x;
    int w    = gtid >> 5;
    int lane = gtid & 31;
    int node = (w << 1) | (lane >> 4);
    int sub  = lane & 15;
    if (node >= N) return;

    const uint2* __restrict__ tin =
        (const uint2*)(g_t + (size_t)kin * MAXN * D);
    uint2* __restrict__ tout =
        (uint2*)(g_t + (size_t)(kin + 1) * MAXN * D);

    float ax, ay, az, aw;
    gather_sum(tin, g_off[node], g_off[node + 1], sub, ax, ay, az, aw);

    float dv = g_dis[node];
    float d2 = dv * dv;          // t_next = dis^2 * sum
    uint2 o;
    __half2 lo = __floats2half2_rn(d2 * ax, d2 * ay);
    __half2 hi = __floats2half2_rn(d2 * az, d2 * aw);
    o.x = *(uint32_t*)&lo;
    o.y = *(uint32_t*)&hi;
    tout[(size_t)node * ROW_U2 + sub] = o;
}

// Layer 4 fused with the final combine:
// out = (e0 + inv*(t1+t2+t3) + dis*sum) / 25   (inv*t4 = inv*dis^2*sum = dis*sum)
__global__ void __launch_bounds__(256)
layer_final_kernel(const float* __restrict__ emb_users,
                   const float* __restrict__ emb_items,
                   float* __restrict__ out, int N, int NU) {
    int gtid = blockIdx.x * blockDim.x + threadIdx.x;
    int w    = gtid >> 5;
    int lane = gtid & 31;
    int node = (w << 1) | (lane >> 4);
    int sub  = lane & 15;
    if (node >= N) return;

    const uint2* __restrict__ t1 = (const uint2*)(g_t + (size_t)1 * MAXN * D);
    const uint2* __restrict__ t2 = (const uint2*)(g_t + (size_t)2 * MAXN * D);
    const uint2* __restrict__ t3 = (const uint2*)(g_t + (size_t)3 * MAXN * D);

    float ax, ay, az, aw;
    gather_sum(t3, g_off[node], g_off[node + 1], sub, ax, ay, az, aw);

    size_t oidx = (size_t)node * ROW_U2 + sub;
    uint2 w1 = t1[oidx];
    uint2 w2 = t2[oidx];
    uint2 w3 = t3[oidx];

    float2 f1a = __half22float2(*(__half2*)&w1.x);
    float2 f1b = __half22float2(*(__half2*)&w1.y);
    float2 f2a = __half22float2(*(__half2*)&w2.x);
    float2 f2b = __half22float2(*(__half2*)&w2.y);
    float2 f3a = __half22float2(*(__half2*)&w3.x);
    float2 f3b = __half22float2(*(__half2*)&w3.y);

    float sx = f1a.x + f2a.x + f3a.x;
    float sy = f1a.y + f2a.y + f3a.y;
    float sz = f1b.x + f2b.x + f3b.x;
    float sw = f1b.y + f2b.y + f3b.y;

    size_t ebase = (size_t)node * D + sub * 4;
    float4 e0;
    if (node < NU) {
        e0 = *(const float4*)&emb_users[ebase];
    } else {
        e0 = *(const float4*)&emb_items[ebase - (size_t)NU * D];
    }

    float dv  = g_dis[node];
    float inv = g_inv[node];
    const float sc = 1.0f / 25.0f;
    float4 r;
    r.x = (e0.x + inv * sx + dv * ax) * sc;
    r.y = (e0.y + inv * sy + dv * ay) * sc;
    r.z = (e0.z + inv * sz + dv * az) * sc;
    r.w = (e0.w + inv * sw + dv * aw) * sc;
    *(float4*)&out[ebase] = r;
}

// -------- launch --------
extern "C" void kernel_launch(void* const* d_in, const int* in_sizes, int n_in,
                              void* d_out, int out_size) {
    const float* emb_users = (const float*)d_in[0];
    const float* emb_items = (const float*)d_in[1];
    const int*   edge      = (const int*)d_in[2];   // int32

    int nu_elems = in_sizes[0];
    int ni_elems = in_sizes[1];
    int E        = in_sizes[2] / 2;
    int NU = nu_elems / D;
    int NI = ni_elems / D;
    int N  = NU + NI;

    const int* src = edge;
    const int* dst = edge + E;
    float* out = (float*)d_out;

    const int T = 256;
    int nScanBlocks = (N + SCAN_T - 1) / SCAN_T;   // 147 <= 148 SMs

    void* deg_ptr = nullptr;
    cudaGetSymbolAddress(&deg_ptr, g_deg);
    cudaMemsetAsync(deg_ptr, 0, (size_t)N * sizeof(int));

    int quads = (E + 3) / 4;
    count_deg_kernel<<<(quads + T - 1) / T, T>>>(dst, E, N);
    scan_fused_kernel<<<nScanBlocks, SCAN_T>>>(emb_users, emb_items, nu_elems, N);
    scatter_kernel<<<(quads + T - 1) / T, T>>>(src, dst, E, N);

    int layer_blocks = (N * 16 + T - 1) / T;   // 2 nodes per warp
    layer_kernel<<<layer_blocks, T>>>(N, 0);   // t0 -> t1
    layer_kernel<<<layer_blocks, T>>>(N, 1);   // t1 -> t2
    layer_kernel<<<layer_blocks, T>>>(N, 2);   // t2 -> t3
    layer_final_kernel<<<layer_blocks, T>>>(emb_users, emb_items, out, N, NU);
}